// round 1
// baseline (speedup 1.0000x reference)
#include <cuda_runtime.h>
#include <math.h>

#define MIN_VALF -1e15f

// ---------------- scratch (device globals; no allocations allowed) ----------
static const long long SZ_QA   = 4096LL * 1536;
static const long long SZ_QB   = 4096LL * 3072;
static const long long SZ_KVF  = 4096LL * 576;
static const long long SZ_KCAT = 4096LL * 576;
static const long long SZ_QCAT = 2LL * 16 * 2048 * 576;
static const long long SZ_SC   = 2LL * 16 * 2048 * 2048;
static const long long SZ_OL   = 2LL * 16 * 2048 * 512;
static const long long SZ_OV   = 4096LL * 2048;

__device__ float g_qa[SZ_QA];
__device__ float g_qb[SZ_QB];
__device__ float g_kvfull[SZ_KVF];
__device__ float g_kcat[SZ_KCAT];
__device__ float g_qcat[SZ_QCAT];
__device__ float g_scores[SZ_SC];
__device__ float g_olat[SZ_OL];
__device__ float g_ov[SZ_OV];

// ---------------- generic batched GEMM: C = A * op(B) (+bias) ---------------
// TRANSB=1: C[m,n] = sum_k A[m,k]*B[n,k]   (both row-major, K contiguous)
// TRANSB=0: C[m,n] = sum_k A[m,k]*B[k,n]
// SCORES:   epilogue v = v*scale + ((n>m || mask[n]==0) ? MIN : 0); tiles fully
//           above the diagonal skip compute and write MIN.
// CAUSALA:  A is lower-triangular (attn weights); truncate K loop at m0+BM.
// Batch z decomposed as (zb, zh) with zh = z % nh; per-operand (b,h) strides.
template<bool TRANSB, bool SCORES, bool CAUSALA>
__global__ void gemm_kernel(
    const float* __restrict__ A, const float* __restrict__ B,
    const float* __restrict__ bias, float* __restrict__ C,
    int M, int N, int K, int lda, int ldb, int ldc,
    long long sAb, long long sAh, long long sBb, long long sBh,
    long long sCb, long long sCh, int nh,
    float scale, const int* __restrict__ mask, int maskld)
{
    int z  = blockIdx.z;
    int zb = z / nh;
    int zh = z - zb * nh;
    const float* Ab = A + zb * sAb + zh * sAh;
    const float* Bb = B + zb * sBb + zh * sBh;
    float*       Cb = C + zb * sCb + zh * sCh;

    int m0 = blockIdx.y * 64;
    int n0 = blockIdx.x * 64;
    int tid = threadIdx.x;          // 256 threads
    int ty = tid >> 4, tx = tid & 15;

    if (SCORES && n0 > m0) {        // whole tile strictly above diagonal
        #pragma unroll
        for (int i = 0; i < 4; i++)
            #pragma unroll
            for (int j = 0; j < 4; j++)
                Cb[(long long)(m0 + ty * 4 + i) * ldc + (n0 + tx * 4 + j)] = MIN_VALF;
        return;
    }

    __shared__ float As[16][65];
    __shared__ float Bs[16][65];

    float acc[4][4];
    #pragma unroll
    for (int i = 0; i < 4; i++)
        #pragma unroll
        for (int j = 0; j < 4; j++) acc[i][j] = 0.f;

    int ar = tid >> 2;              // 0..63
    int ac = (tid & 3) * 4;         // 0,4,8,12
    int kend = CAUSALA ? min(K, m0 + 64) : K;

    for (int k0 = 0; k0 < kend; k0 += 16) {
        float4 av = *(const float4*)(Ab + (long long)(m0 + ar) * lda + (k0 + ac));
        As[ac + 0][ar] = av.x; As[ac + 1][ar] = av.y;
        As[ac + 2][ar] = av.z; As[ac + 3][ar] = av.w;
        if (TRANSB) {
            float4 bv = *(const float4*)(Bb + (long long)(n0 + ar) * ldb + (k0 + ac));
            Bs[ac + 0][ar] = bv.x; Bs[ac + 1][ar] = bv.y;
            Bs[ac + 2][ar] = bv.z; Bs[ac + 3][ar] = bv.w;
        } else {
            int kr = tid >> 4;          // 0..15
            int nc = (tid & 15) * 4;    // 0..60
            float4 bv = *(const float4*)(Bb + (long long)(k0 + kr) * ldb + (n0 + nc));
            Bs[kr][nc + 0] = bv.x; Bs[kr][nc + 1] = bv.y;
            Bs[kr][nc + 2] = bv.z; Bs[kr][nc + 3] = bv.w;
        }
        __syncthreads();
        #pragma unroll
        for (int k = 0; k < 16; k++) {
            float a[4], b[4];
            #pragma unroll
            for (int i = 0; i < 4; i++) a[i] = As[k][ty * 4 + i];
            #pragma unroll
            for (int j = 0; j < 4; j++) b[j] = Bs[k][tx * 4 + j];
            #pragma unroll
            for (int i = 0; i < 4; i++)
                #pragma unroll
                for (int j = 0; j < 4; j++) acc[i][j] += a[i] * b[j];
        }
        __syncthreads();
    }

    const int* mrow = SCORES ? (mask + (long long)zb * maskld) : (const int*)0;
    #pragma unroll
    for (int i = 0; i < 4; i++) {
        int m = m0 + ty * 4 + i;
        #pragma unroll
        for (int j = 0; j < 4; j++) {
            int n = n0 + tx * 4 + j;
            float v = acc[i][j];
            if (bias) v += bias[n];
            if (SCORES) {
                v *= scale;
                if (n > m || mrow[n] == 0) v += MIN_VALF;
            }
            Cb[(long long)m * ldc + n] = v;
        }
    }
}

// ---------------- RMSNorm (in-place over rows) -------------------------------
__global__ void rmsnorm_kernel(float* __restrict__ x, const float* __restrict__ w, int D)
{
    long long row = blockIdx.x;
    float* p = x + row * D;
    __shared__ float red[256];
    int tid = threadIdx.x;
    float ss = 0.f;
    for (int i = tid; i < D; i += 256) { float v = p[i]; ss += v * v; }
    red[tid] = ss; __syncthreads();
    for (int s = 128; s > 0; s >>= 1) { if (tid < s) red[tid] += red[tid + s]; __syncthreads(); }
    float r = rsqrtf(red[0] / (float)D + 1e-6f);
    for (int i = tid; i < D; i += 256) p[i] = w[i] * p[i] * r;
}

// ---------------- KV prep: rmsnorm kv, rope k_pe -> g_kcat[row][576] --------
__global__ void prep_kv_kernel(const float* __restrict__ kvfull,
                               const float* __restrict__ w,
                               float* __restrict__ kcat)
{
    int row = blockIdx.x;                // b*2048 + t
    const float* in = kvfull + (long long)row * 576;
    float* out = kcat + (long long)row * 576;
    __shared__ float red[256];
    int tid = threadIdx.x;
    float ss = 0.f;
    for (int i = tid; i < 512; i += 256) { float v = in[i]; ss += v * v; }
    red[tid] = ss; __syncthreads();
    for (int s = 128; s > 0; s >>= 1) { if (tid < s) red[tid] += red[tid + s]; __syncthreads(); }
    float r = rsqrtf(red[0] / 512.0f + 1e-6f);
    for (int i = tid; i < 512; i += 256) out[i] = w[i] * in[i] * r;

    int pos = row & 2047;
    if (tid < 64) {
        int j = tid, jm = j & 31;
        float inv = (float)pow(10000.0, -(double)(2 * jm) / 64.0);
        float ang = (float)pos * inv;
        float c = cosf(ang), si = sinf(ang);
        float xj = in[512 + j];
        float other = (j < 32) ? -in[512 + j + 32] : in[512 + j - 32];
        out[512 + j] = xj * c + other * si;
    }
}

// ---------------- Q_pe rope: g_qb pe-slice -> g_qcat[...,512:576] ------------
__global__ void prep_qpe_kernel(const float* __restrict__ qb, float* __restrict__ qcat)
{
    int row = blockIdx.x;                // b*2048 + s
    int pos = row & 2047;
    int b = row >> 11;
    int tid = threadIdx.x;
    for (int idx = tid; idx < 16 * 64; idx += blockDim.x) {
        int h = idx >> 6, j = idx & 63, jm = j & 31;
        float inv = (float)pow(10000.0, -(double)(2 * jm) / 64.0);
        float ang = (float)pos * inv;
        float c = cosf(ang), si = sinf(ang);
        const float* qp = qb + (long long)row * 3072 + h * 192 + 128;
        float xj = qp[j];
        float other = (j < 32) ? -qp[j + 32] : qp[j - 32];
        qcat[((long long)(b * 16 + h) * 2048 + pos) * 576 + 512 + j] = xj * c + other * si;
    }
}

// ---------------- row softmax over T=2048 (in place) -------------------------
__global__ void softmax_kernel(float* __restrict__ sc)
{
    long long row = blockIdx.x;
    float* p = sc + row * 2048;
    __shared__ float red[256];
    int tid = threadIdx.x;
    float m = -3.0e38f;
    for (int i = tid; i < 2048; i += 256) m = fmaxf(m, p[i]);
    red[tid] = m; __syncthreads();
    for (int s = 128; s > 0; s >>= 1) { if (tid < s) red[tid] = fmaxf(red[tid], red[tid + s]); __syncthreads(); }
    m = red[0]; __syncthreads();
    float sum = 0.f;
    for (int i = tid; i < 2048; i += 256) { float e = expf(p[i] - m); p[i] = e; sum += e; }
    red[tid] = sum; __syncthreads();
    for (int s = 128; s > 0; s >>= 1) { if (tid < s) red[tid] += red[tid + s]; __syncthreads(); }
    float inv = 1.0f / red[0];
    for (int i = tid; i < 2048; i += 256) p[i] *= inv;
}

// ---------------- launch -----------------------------------------------------
extern "C" void kernel_launch(void* const* d_in, const int* in_sizes, int n_in,
                              void* d_out, int out_size)
{
    const float* x        = (const float*)d_in[0];
    const int*   mask     = (const int*)  d_in[1];
    const float* wq_a_w   = (const float*)d_in[2];
    const float* wq_a_b   = (const float*)d_in[3];
    const float* q_norm_w = (const float*)d_in[4];
    const float* wq_b_w   = (const float*)d_in[5];
    const float* wq_b_b   = (const float*)d_in[6];
    const float* wkv_a_w  = (const float*)d_in[7];
    const float* wkv_a_b  = (const float*)d_in[8];
    const float* kv_norm_w= (const float*)d_in[9];
    const float* wkv_b_w  = (const float*)d_in[10];
    const float* wo_w     = (const float*)d_in[11];
    const float* wo_b     = (const float*)d_in[12];
    float* out = (float*)d_out;

    float *qa, *qb, *kvf, *kcat, *qcat, *sc, *ol, *ov;
    cudaGetSymbolAddress((void**)&qa,   g_qa);
    cudaGetSymbolAddress((void**)&qb,   g_qb);
    cudaGetSymbolAddress((void**)&kvf,  g_kvfull);
    cudaGetSymbolAddress((void**)&kcat, g_kcat);
    cudaGetSymbolAddress((void**)&qcat, g_qcat);
    cudaGetSymbolAddress((void**)&sc,   g_scores);
    cudaGetSymbolAddress((void**)&ol,   g_olat);
    cudaGetSymbolAddress((void**)&ov,   g_ov);

    const float scale = rsqrtf(192.0f);

    // 1) q_a = x @ wq_a^T + b        [4096,1536] K=2048
    gemm_kernel<true,false,false><<<dim3(24,64,1),256>>>(
        x, wq_a_w, wq_a_b, qa, 4096,1536,2048, 2048,2048,1536,
        0,0,0,0,0,0, 1, 0.f, 0, 0);
    // 2) rmsnorm(q_a)
    rmsnorm_kernel<<<4096,256>>>(qa, q_norm_w, 1536);
    // 3) q_b = q_a @ wq_b^T + b      [4096,3072] K=1536
    gemm_kernel<true,false,false><<<dim3(48,64,1),256>>>(
        qa, wq_b_w, wq_b_b, qb, 4096,3072,1536, 1536,1536,3072,
        0,0,0,0,0,0, 1, 0.f, 0, 0);
    // 4) kv_full = x @ wkv_a^T + b   [4096,576] K=2048
    gemm_kernel<true,false,false><<<dim3(9,64,1),256>>>(
        x, wkv_a_w, wkv_a_b, kvf, 4096,576,2048, 2048,2048,576,
        0,0,0,0,0,0, 1, 0.f, 0, 0);
    // 5) kv rmsnorm + k_pe rope -> kcat
    prep_kv_kernel<<<4096,256>>>(kvf, kv_norm_w, kcat);
    // 6) q_pe rope -> qcat[...,512:576]
    prep_qpe_kernel<<<4096,256>>>(qb, qcat);
    // 7) q_lat[b,h] = q_nope[b,:,h,:] @ wkv_b[h,:128,:]  (NN) -> qcat[...,0:512]
    gemm_kernel<false,false,false><<<dim3(8,32,32),256>>>(
        qb, wkv_b_w, 0, qcat, 2048,512,128, 3072,512,576,
        2048LL*3072, 192, 0, 256LL*512, 16LL*2048*576, 2048LL*576, 16,
        0.f, 0, 0);
    // 8) scores[b,h] = qcat @ kcat^T * scale + mask   (NT, causal-skip)
    gemm_kernel<true,true,false><<<dim3(32,32,32),256>>>(
        qcat, kcat, 0, sc, 2048,2048,576, 576,576,2048,
        16LL*2048*576, 2048LL*576, 2048LL*576, 0,
        16LL*2048*2048, 2048LL*2048, 16, scale, mask, 2048);
    // 9) softmax rows
    softmax_kernel<<<2*16*2048,256>>>(sc);
    // 10) olat[b,h] = attn @ kv      (NN, causal K-truncation)
    gemm_kernel<false,false,true><<<dim3(8,32,32),256>>>(
        sc, kcat, 0, ol, 2048,512,2048, 2048,576,512,
        16LL*2048*2048, 2048LL*2048, 2048LL*576, 0,
        16LL*2048*512, 2048LL*512, 16, 0.f, 0, 0);
    // 11) ov[b,s,h*128+d] = olat @ wkv_b[h,128:,:]^T   (NT)
    gemm_kernel<true,false,false><<<dim3(2,32,32),256>>>(
        ol, wkv_b_w + 128LL*512, 0, ov, 2048,128,512, 512,512,2048,
        16LL*2048*512, 2048LL*512, 0, 256LL*512,
        2048LL*2048, 128, 16, 0.f, 0, 0);
    // 12) out = ov @ wo^T + b        [4096,2048] K=2048
    gemm_kernel<true,false,false><<<dim3(32,64,1),256>>>(
        ov, wo_w, wo_b, out, 4096,2048,2048, 2048,2048,2048,
        0,0,0,0,0,0, 1, 0.f, 0, 0);
}

// round 2
// speedup vs baseline: 1.3349x; 1.3349x over previous
#include <cuda_runtime.h>
#include <math.h>

#define MIN_VALF -1e15f

// ---------------- scratch (device globals; no allocations allowed) ----------
static const long long SZ_QA   = 4096LL * 1536;
static const long long SZ_QB   = 4096LL * 3072;
static const long long SZ_KVF  = 4096LL * 576;
static const long long SZ_KCAT = 4096LL * 576;
static const long long SZ_QCAT = 2LL * 16 * 2048 * 576;
static const long long SZ_SC   = 2LL * 16 * 2048 * 2048;
static const long long SZ_OL   = 2LL * 16 * 2048 * 512;
static const long long SZ_OV   = 4096LL * 2048;

__device__ float g_qa[SZ_QA];
__device__ float g_qb[SZ_QB];
__device__ float g_kvfull[SZ_KVF];
__device__ float g_kcat[SZ_KCAT];
__device__ float g_qcat[SZ_QCAT];
__device__ float g_scores[SZ_SC];
__device__ float g_olat[SZ_OL];
__device__ float g_ov[SZ_OV];

// ---------------- batched GEMM: C = A * op(B) (+bias) -----------------------
// 128 x BN tile, BK=8, 256 threads, 8 x (BN/16) per-thread microtile,
// double-buffered shared memory. All dims assumed to divide tiles exactly.
// TRANSB=1: C[m,n] = sum_k A[m,k]*B[n,k]
// TRANSB=0: C[m,n] = sum_k A[m,k]*B[k,n]
// SCORES:   epilogue v = v*scale + ((n>m || mask[n]==0) ? MIN : 0); tiles fully
//           above the diagonal skip compute and just write MIN.
// CAUSALA:  A is lower-triangular (attn weights); truncate K loop at m0+128.
template<int BN, bool TRANSB, bool SCORES, bool CAUSALA>
__global__ __launch_bounds__(256, 2)
void gemm_kernel(
    const float* __restrict__ A, const float* __restrict__ B,
    const float* __restrict__ bias, float* __restrict__ C,
    int M, int N, int K, int lda, int ldb, int ldc,
    long long sAb, long long sAh, long long sBb, long long sBh,
    long long sCb, long long sCh, int nh,
    float scale, const int* __restrict__ mask, int maskld)
{
    constexpr int TN = BN / 16;          // 8 (BN=128) or 4 (BN=64)
    int z  = blockIdx.z;
    int zb = z / nh;
    int zh = z - zb * nh;
    const float* Ab = A + zb * sAb + zh * sAh;
    const float* Bb = B + zb * sBb + zh * sBh;
    float*       Cb = C + zb * sCb + zh * sCh;

    int m0 = blockIdx.y * 128;
    int n0 = blockIdx.x * BN;
    int tid = threadIdx.x;
    int tx = tid & 15, ty = tid >> 4;

    if (SCORES && n0 >= m0 + 128) {      // whole tile strictly above diagonal
        float4 mv = make_float4(MIN_VALF, MIN_VALF, MIN_VALF, MIN_VALF);
        #pragma unroll
        for (int i = 0; i < 8; i++) {
            float* crow = Cb + (long long)(m0 + ty * 8 + i) * ldc + n0 + tx * TN;
            #pragma unroll
            for (int j4 = 0; j4 < TN / 4; j4++) ((float4*)crow)[j4] = mv;
        }
        return;
    }

    __shared__ float As[2][8][128];
    __shared__ float Bs[2][8][BN];

    float acc[8][TN];
    #pragma unroll
    for (int i = 0; i < 8; i++)
        #pragma unroll
        for (int j = 0; j < TN; j++) acc[i][j] = 0.f;

    int kend = CAUSALA ? min(K, m0 + 128) : K;
    int nkt  = kend >> 3;

    // A global-load mapping: thread -> (row = tid/2, col = (tid&1)*4)
    int arow = tid >> 1;
    int acol = (tid & 1) * 4;
    const float* Aptr = Ab + (long long)(m0 + arow) * lda + acol;

    // B global-load mapping
    const float* Bptr;
    int br = 0, bc = 0, bk = 0, bn = 0;
    bool bact;
    if (TRANSB) {
        br = tid >> 1;                   // n-index within tile
        bc = (tid & 1) * 4;              // k-offset
        bact = (tid < 2 * BN);
        Bptr = Bb + (long long)(n0 + br) * ldb + bc;
    } else {
        bk = tid / (BN / 4);
        bn = (tid % (BN / 4)) * 4;
        bact = (tid < 2 * BN);
        Bptr = Bb + (long long)bk * ldb + n0 + bn;
    }

    float4 aReg = *(const float4*)Aptr;
    float4 bReg = make_float4(0.f, 0.f, 0.f, 0.f);
    if (bact) bReg = *(const float4*)Bptr;

    // store tile 0
    {
        As[0][acol + 0][arow] = aReg.x; As[0][acol + 1][arow] = aReg.y;
        As[0][acol + 2][arow] = aReg.z; As[0][acol + 3][arow] = aReg.w;
        if (bact) {
            if (TRANSB) {
                Bs[0][bc + 0][br] = bReg.x; Bs[0][bc + 1][br] = bReg.y;
                Bs[0][bc + 2][br] = bReg.z; Bs[0][bc + 3][br] = bReg.w;
            } else {
                *(float4*)&Bs[0][bk][bn] = bReg;
            }
        }
    }
    __syncthreads();

    int buf = 0;
    for (int kt = 0; kt < nkt; kt++) {
        bool more = (kt + 1 < nkt);
        if (more) {
            Aptr += 8;
            aReg = *(const float4*)Aptr;
            if (bact) {
                if (TRANSB) Bptr += 8; else Bptr += (long long)8 * ldb;
                bReg = *(const float4*)Bptr;
            }
        }

        #pragma unroll
        for (int k = 0; k < 8; k++) {
            float a[8], b[TN];
            *(float4*)&a[0] = *(const float4*)&As[buf][k][ty * 8];
            *(float4*)&a[4] = *(const float4*)&As[buf][k][ty * 8 + 4];
            #pragma unroll
            for (int j4 = 0; j4 < TN / 4; j4++)
                *(float4*)&b[j4 * 4] = *(const float4*)&Bs[buf][k][tx * TN + j4 * 4];
            #pragma unroll
            for (int i = 0; i < 8; i++)
                #pragma unroll
                for (int j = 0; j < TN; j++)
                    acc[i][j] += a[i] * b[j];
        }

        if (more) {
            int nb = buf ^ 1;
            As[nb][acol + 0][arow] = aReg.x; As[nb][acol + 1][arow] = aReg.y;
            As[nb][acol + 2][arow] = aReg.z; As[nb][acol + 3][arow] = aReg.w;
            if (bact) {
                if (TRANSB) {
                    Bs[nb][bc + 0][br] = bReg.x; Bs[nb][bc + 1][br] = bReg.y;
                    Bs[nb][bc + 2][br] = bReg.z; Bs[nb][bc + 3][br] = bReg.w;
                } else {
                    *(float4*)&Bs[nb][bk][bn] = bReg;
                }
            }
            __syncthreads();
            buf = nb;
        }
    }

    const int* mrow = SCORES ? (mask + (long long)zb * maskld) : (const int*)0;
    #pragma unroll
    for (int i = 0; i < 8; i++) {
        int m = m0 + ty * 8 + i;
        float* crow = Cb + (long long)m * ldc + n0 + tx * TN;
        float vout[TN];
        #pragma unroll
        for (int j = 0; j < TN; j++) {
            int n = n0 + tx * TN + j;
            float v = acc[i][j];
            if (bias) v += bias[n];
            if (SCORES) {
                v *= scale;
                if (n > m || mrow[n] == 0) v += MIN_VALF;
            }
            vout[j] = v;
        }
        #pragma unroll
        for (int j4 = 0; j4 < TN / 4; j4++)
            ((float4*)crow)[j4] = *(float4*)&vout[j4 * 4];
    }
}

// ---------------- RMSNorm (in-place over rows) -------------------------------
__global__ void rmsnorm_kernel(float* __restrict__ x, const float* __restrict__ w, int D)
{
    long long row = blockIdx.x;
    float* p = x + row * D;
    __shared__ float red[256];
    int tid = threadIdx.x;
    float ss = 0.f;
    for (int i = tid; i < D; i += 256) { float v = p[i]; ss += v * v; }
    red[tid] = ss; __syncthreads();
    for (int s = 128; s > 0; s >>= 1) { if (tid < s) red[tid] += red[tid + s]; __syncthreads(); }
    float r = rsqrtf(red[0] / (float)D + 1e-6f);
    for (int i = tid; i < D; i += 256) p[i] = w[i] * p[i] * r;
}

// ---------------- KV prep: rmsnorm kv, rope k_pe -> g_kcat[row][576] --------
__global__ void prep_kv_kernel(const float* __restrict__ kvfull,
                               const float* __restrict__ w,
                               float* __restrict__ kcat)
{
    int row = blockIdx.x;                // b*2048 + t
    const float* in = kvfull + (long long)row * 576;
    float* out = kcat + (long long)row * 576;
    __shared__ float red[256];
    int tid = threadIdx.x;
    float ss = 0.f;
    for (int i = tid; i < 512; i += 256) { float v = in[i]; ss += v * v; }
    red[tid] = ss; __syncthreads();
    for (int s = 128; s > 0; s >>= 1) { if (tid < s) red[tid] += red[tid + s]; __syncthreads(); }
    float r = rsqrtf(red[0] / 512.0f + 1e-6f);
    for (int i = tid; i < 512; i += 256) out[i] = w[i] * in[i] * r;

    int pos = row & 2047;
    if (tid < 64) {
        int j = tid, jm = j & 31;
        float inv = (float)pow(10000.0, -(double)(2 * jm) / 64.0);
        float ang = (float)pos * inv;
        float c = cosf(ang), si = sinf(ang);
        float xj = in[512 + j];
        float other = (j < 32) ? -in[512 + j + 32] : in[512 + j - 32];
        out[512 + j] = xj * c + other * si;
    }
}

// ---------------- Q_pe rope: g_qb pe-slice -> g_qcat[...,512:576] ------------
__global__ void prep_qpe_kernel(const float* __restrict__ qb, float* __restrict__ qcat)
{
    int row = blockIdx.x;                // b*2048 + s
    int pos = row & 2047;
    int b = row >> 11;
    int tid = threadIdx.x;
    for (int idx = tid; idx < 16 * 64; idx += blockDim.x) {
        int h = idx >> 6, j = idx & 63, jm = j & 31;
        float inv = (float)pow(10000.0, -(double)(2 * jm) / 64.0);
        float ang = (float)pos * inv;
        float c = cosf(ang), si = sinf(ang);
        const float* qp = qb + (long long)row * 3072 + h * 192 + 128;
        float xj = qp[j];
        float other = (j < 32) ? -qp[j + 32] : qp[j - 32];
        qcat[((long long)(b * 16 + h) * 2048 + pos) * 576 + 512 + j] = xj * c + other * si;
    }
}

// ---------------- row softmax over T=2048 (in place) -------------------------
__global__ void softmax_kernel(float* __restrict__ sc)
{
    long long row = blockIdx.x;
    float* p = sc + row * 2048;
    __shared__ float red[256];
    int tid = threadIdx.x;
    float m = -3.0e38f;
    for (int i = tid; i < 2048; i += 256) m = fmaxf(m, p[i]);
    red[tid] = m; __syncthreads();
    for (int s = 128; s > 0; s >>= 1) { if (tid < s) red[tid] = fmaxf(red[tid], red[tid + s]); __syncthreads(); }
    m = red[0]; __syncthreads();
    float sum = 0.f;
    for (int i = tid; i < 2048; i += 256) { float e = expf(p[i] - m); p[i] = e; sum += e; }
    red[tid] = sum; __syncthreads();
    for (int s = 128; s > 0; s >>= 1) { if (tid < s) red[tid] += red[tid + s]; __syncthreads(); }
    float inv = 1.0f / red[0];
    for (int i = tid; i < 2048; i += 256) p[i] *= inv;
}

// ---------------- launch -----------------------------------------------------
extern "C" void kernel_launch(void* const* d_in, const int* in_sizes, int n_in,
                              void* d_out, int out_size)
{
    const float* x        = (const float*)d_in[0];
    const int*   mask     = (const int*)  d_in[1];
    const float* wq_a_w   = (const float*)d_in[2];
    const float* wq_a_b   = (const float*)d_in[3];
    const float* q_norm_w = (const float*)d_in[4];
    const float* wq_b_w   = (const float*)d_in[5];
    const float* wq_b_b   = (const float*)d_in[6];
    const float* wkv_a_w  = (const float*)d_in[7];
    const float* wkv_a_b  = (const float*)d_in[8];
    const float* kv_norm_w= (const float*)d_in[9];
    const float* wkv_b_w  = (const float*)d_in[10];
    const float* wo_w     = (const float*)d_in[11];
    const float* wo_b     = (const float*)d_in[12];
    float* out = (float*)d_out;

    float *qa, *qb, *kvf, *kcat, *qcat, *sc, *ol, *ov;
    cudaGetSymbolAddress((void**)&qa,   g_qa);
    cudaGetSymbolAddress((void**)&qb,   g_qb);
    cudaGetSymbolAddress((void**)&kvf,  g_kvfull);
    cudaGetSymbolAddress((void**)&kcat, g_kcat);
    cudaGetSymbolAddress((void**)&qcat, g_qcat);
    cudaGetSymbolAddress((void**)&sc,   g_scores);
    cudaGetSymbolAddress((void**)&ol,   g_olat);
    cudaGetSymbolAddress((void**)&ov,   g_ov);

    const float scale = rsqrtf(192.0f);

    // 1) q_a = x @ wq_a^T + b        [4096,1536] K=2048
    gemm_kernel<128,true,false,false><<<dim3(12,32,1),256>>>(
        x, wq_a_w, wq_a_b, qa, 4096,1536,2048, 2048,2048,1536,
        0,0,0,0,0,0, 1, 0.f, 0, 0);
    // 2) rmsnorm(q_a)
    rmsnorm_kernel<<<4096,256>>>(qa, q_norm_w, 1536);
    // 3) q_b = q_a @ wq_b^T + b      [4096,3072] K=1536
    gemm_kernel<128,true,false,false><<<dim3(24,32,1),256>>>(
        qa, wq_b_w, wq_b_b, qb, 4096,3072,1536, 1536,1536,3072,
        0,0,0,0,0,0, 1, 0.f, 0, 0);
    // 4) kv_full = x @ wkv_a^T + b   [4096,576] K=2048 (N=576 -> BN=64)
    gemm_kernel<64,true,false,false><<<dim3(9,32,1),256>>>(
        x, wkv_a_w, wkv_a_b, kvf, 4096,576,2048, 2048,2048,576,
        0,0,0,0,0,0, 1, 0.f, 0, 0);
    // 5) kv rmsnorm + k_pe rope -> kcat
    prep_kv_kernel<<<4096,256>>>(kvf, kv_norm_w, kcat);
    // 6) q_pe rope -> qcat[...,512:576]
    prep_qpe_kernel<<<4096,256>>>(qb, qcat);
    // 7) q_lat[b,h] = q_nope[b,:,h,:] @ wkv_b[h,:128,:]  (NN) -> qcat[...,0:512]
    gemm_kernel<128,false,false,false><<<dim3(4,16,32),256>>>(
        qb, wkv_b_w, 0, qcat, 2048,512,128, 3072,512,576,
        2048LL*3072, 192, 0, 256LL*512, 16LL*2048*576, 2048LL*576, 16,
        0.f, 0, 0);
    // 8) scores[b,h] = qcat @ kcat^T * scale + mask   (NT, causal-skip)
    gemm_kernel<128,true,true,false><<<dim3(16,16,32),256>>>(
        qcat, kcat, 0, sc, 2048,2048,576, 576,576,2048,
        16LL*2048*576, 2048LL*576, 2048LL*576, 0,
        16LL*2048*2048, 2048LL*2048, 16, scale, mask, 2048);
    // 9) softmax rows
    softmax_kernel<<<2*16*2048,256>>>(sc);
    // 10) olat[b,h] = attn @ kv      (NN, causal K-truncation)
    gemm_kernel<128,false,false,true><<<dim3(4,16,32),256>>>(
        sc, kcat, 0, ol, 2048,512,2048, 2048,576,512,
        16LL*2048*2048, 2048LL*2048, 2048LL*576, 0,
        16LL*2048*512, 2048LL*512, 16, 0.f, 0, 0);
    // 11) ov[b,s,h*128+d] = olat @ wkv_b[h,128:,:]^T   (NT)
    gemm_kernel<128,true,false,false><<<dim3(1,16,32),256>>>(
        ol, wkv_b_w + 128LL*512, 0, ov, 2048,128,512, 512,512,2048,
        16LL*2048*512, 2048LL*512, 0, 256LL*512,
        2048LL*2048, 128, 16, 0.f, 0, 0);
    // 12) out = ov @ wo^T + b        [4096,2048] K=2048
    gemm_kernel<128,true,false,false><<<dim3(16,32,1),256>>>(
        ov, wo_w, wo_b, out, 4096,2048,2048, 2048,2048,2048,
        0,0,0,0,0,0, 1, 0.f, 0, 0);
}

// round 4
// speedup vs baseline: 2.7317x; 2.0464x over previous
#include <cuda_runtime.h>
#include <cuda_bf16.h>
#include <math.h>
#include <stdint.h>

#define MIN_VALF -1e15f

// ---------------- scratch (device globals) -----------------------------------
__device__ float g_qa[4096LL * 1536];
__device__ float g_qb[4096LL * 3072];
__device__ float g_kvfull[4096LL * 576];
__device__ float g_kcat[4096LL * 576];
__device__ float g_qcat[2LL * 16 * 2048 * 576];
__device__ float g_scores[2LL * 16 * 2048 * 2048];
__device__ float g_olat[2LL * 16 * 2048 * 512];
__device__ float g_ov[4096LL * 2048];
__device__ float g_kcatT[2LL * 512 * 2048];
__device__ float g_wT1[16LL * 512 * 128];

// ---------------- helpers ----------------------------------------------------
__device__ __forceinline__ uint32_t smem_u32(const void* p) {
    uint32_t a;
    asm("{ .reg .u64 t; cvta.to.shared.u64 t, %1; cvt.u32.u64 %0, t; }" : "=r"(a) : "l"(p));
    return a;
}
__device__ __forceinline__ uint32_t swz(uint32_t o) { return o ^ ((o >> 3) & 0x70); }

__device__ __forceinline__ void ldm_x4(uint32_t& r0, uint32_t& r1, uint32_t& r2, uint32_t& r3,
                                       uint32_t addr) {
    asm volatile("ldmatrix.sync.aligned.m8n8.x4.shared.b16 {%0,%1,%2,%3}, [%4];"
                 : "=r"(r0), "=r"(r1), "=r"(r2), "=r"(r3) : "r"(addr));
}

__device__ __forceinline__ void mma_bf16(float* d, const uint32_t* a, uint32_t b0, uint32_t b1) {
    asm volatile("mma.sync.aligned.m16n8k16.row.col.f32.bf16.bf16.f32 "
                 "{%0,%1,%2,%3},{%4,%5,%6,%7},{%8,%9},{%0,%1,%2,%3};"
                 : "+f"(d[0]), "+f"(d[1]), "+f"(d[2]), "+f"(d[3])
                 : "r"(a[0]), "r"(a[1]), "r"(a[2]), "r"(a[3]), "r"(b0), "r"(b1));
}

// split fp32x4 -> hi/lo bf16x2 pairs and store (8B each, swizzle-safe)
__device__ __forceinline__ void cvt_store(char* hi, char* lo, float4 v) {
    __nv_bfloat162 h01 = __floats2bfloat162_rn(v.x, v.y);
    __nv_bfloat162 h23 = __floats2bfloat162_rn(v.z, v.w);
    float r0 = v.x - __low2float(h01), r1 = v.y - __high2float(h01);
    float r2 = v.z - __low2float(h23), r3 = v.w - __high2float(h23);
    __nv_bfloat162 l01 = __floats2bfloat162_rn(r0, r1);
    __nv_bfloat162 l23 = __floats2bfloat162_rn(r2, r3);
    uint2 hw, lw;
    hw.x = *(uint32_t*)&h01; hw.y = *(uint32_t*)&h23;
    lw.x = *(uint32_t*)&l01; lw.y = *(uint32_t*)&l23;
    *(uint2*)hi = hw;
    *(uint2*)lo = lw;
}

// ---------------- tensor-core GEMM: C[m,n] = sum_k A[m,k]*B[n,k] -------------
// 128 x BN tile, BK=64, 8 warps, mma.sync m16n8k16 bf16 with 2-term split
// (3 passes: hi*hi + hi*lo + lo*hi), fp32 accum. SW128-swizzled smem planes.
template<int BN, bool SCORES, bool CAUSALA>
__global__ __launch_bounds__(256, 1)
void tgemm(const float* __restrict__ A, const float* __restrict__ B,
           const float* __restrict__ bias, float* __restrict__ C,
           int K, int lda, int ldb, int ldc,
           long long sAb, long long sAh, long long sBb, long long sBh,
           long long sCb, long long sCh, int nh,
           float scale, const int* __restrict__ mask, int maskld)
{
    constexpr int APB = 128 * 128;           // A plane bytes (128 rows x 128B)
    constexpr int BPB = BN * 128;
    constexpr int STAGE = 2 * APB + 2 * BPB;
    constexpr int NWM = (BN == 128) ? 4 : 8; // warps along M
    constexpr int WM  = 128 / NWM;           // rows per warp (32 or 16)
    constexpr int WN  = (BN == 128) ? 64 : 64; // cols per warp
    constexpr int MI  = WM / 16;             // 2 or 1
    constexpr int NI  = WN / 8;              // 8

    extern __shared__ __align__(1024) char smem[];

    int tid = threadIdx.x;
    int wid = tid >> 5, lane = tid & 31;
    int warp_m = wid % NWM, warp_n = wid / NWM;

    int z = blockIdx.z, zb = z / nh, zh = z - zb * nh;
    const float* Ab = A + zb * sAb + zh * sAh;
    const float* Bb = B + zb * sBb + zh * sBh;
    float*       Cb = C + zb * sCb + zh * sCh;
    int m0 = blockIdx.y * 128, n0 = blockIdx.x * BN;

    if (SCORES && n0 >= m0 + 128) {          // tile fully above diagonal
        float4 mv = make_float4(MIN_VALF, MIN_VALF, MIN_VALF, MIN_VALF);
        constexpr int C4 = BN / 4;
        #pragma unroll
        for (int j = 0; j < 128 * C4 / 256; j++) {
            int i4 = tid + 256 * j;
            int r = i4 / C4, c4 = i4 % C4;
            *(float4*)(Cb + (long long)(m0 + r) * ldc + n0 + c4 * 4) = mv;
        }
        return;
    }

    int kend = CAUSALA ? min(K, m0 + 128) : K;
    int nt = kend >> 6;

    const float* Ap = Ab + (long long)m0 * lda;
    const float* Bp = Bb + (long long)n0 * ldb;

    float acc[MI][NI][4];
    #pragma unroll
    for (int mi = 0; mi < MI; mi++)
        #pragma unroll
        for (int ni = 0; ni < NI; ni++)
            #pragma unroll
            for (int q = 0; q < 4; q++) acc[mi][ni][q] = 0.f;

    float4 ra[8], rb[BN / 16];

    // ---- load tile 0 and store to stage 0
    #pragma unroll
    for (int j = 0; j < 8; j++) {
        int i4 = tid + 256 * j; int r = i4 >> 4, c4 = i4 & 15;
        ra[j] = *(const float4*)(Ap + (long long)r * lda + c4 * 4);
    }
    #pragma unroll
    for (int j = 0; j < BN / 16; j++) {
        int i4 = tid + 256 * j; int r = i4 >> 4, c4 = i4 & 15;
        rb[j] = *(const float4*)(Bp + (long long)r * ldb + c4 * 4);
    }
    {
        char* st = smem;
        #pragma unroll
        for (int j = 0; j < 8; j++) {
            int i4 = tid + 256 * j; int r = i4 >> 4, c4 = i4 & 15;
            uint32_t off = swz(r * 128 + c4 * 8);
            cvt_store(st + off, st + APB + off, ra[j]);
        }
        #pragma unroll
        for (int j = 0; j < BN / 16; j++) {
            int i4 = tid + 256 * j; int r = i4 >> 4, c4 = i4 & 15;
            uint32_t off = swz(r * 128 + c4 * 8);
            cvt_store(st + 2 * APB + off, st + 2 * APB + BPB + off, rb[j]);
        }
    }
    __syncthreads();

    for (int i = 0; i < nt; i++) {
        int buf = i & 1;
        bool more = (i + 1 < nt);
        if (more) {
            int k0 = (i + 1) << 6;
            #pragma unroll
            for (int j = 0; j < 8; j++) {
                int i4 = tid + 256 * j; int r = i4 >> 4, c4 = i4 & 15;
                ra[j] = *(const float4*)(Ap + (long long)r * lda + k0 + c4 * 4);
            }
            #pragma unroll
            for (int j = 0; j < BN / 16; j++) {
                int i4 = tid + 256 * j; int r = i4 >> 4, c4 = i4 & 15;
                rb[j] = *(const float4*)(Bp + (long long)r * ldb + k0 + c4 * 4);
            }
        }

        // ---- compute on buffer `buf`
        {
            uint32_t ahi = smem_u32(smem) + buf * STAGE;
            uint32_t alo = ahi + APB;
            uint32_t bhi = ahi + 2 * APB;
            uint32_t blo = bhi + BPB;
            #pragma unroll
            for (int kk = 0; kk < 4; kk++) {
                uint32_t Ah[MI][4], Al[MI][4];
                uint32_t cb = kk * 32 + ((lane >> 4) & 1) * 16;
                int rsel = (lane & 7) + ((lane >> 3) & 1) * 8;
                #pragma unroll
                for (int mi = 0; mi < MI; mi++) {
                    int rr = warp_m * WM + mi * 16 + rsel;
                    uint32_t o = swz(rr * 128 + cb);
                    ldm_x4(Ah[mi][0], Ah[mi][1], Ah[mi][2], Ah[mi][3], ahi + o);
                    ldm_x4(Al[mi][0], Al[mi][1], Al[mi][2], Al[mi][3], alo + o);
                }
                #pragma unroll
                for (int np = 0; np < NI / 2; np++) {
                    int rr = warp_n * WN + np * 16 + rsel;
                    uint32_t o = swz(rr * 128 + cb);
                    uint32_t Bh[4], Bl[4];
                    ldm_x4(Bh[0], Bh[1], Bh[2], Bh[3], bhi + o);
                    ldm_x4(Bl[0], Bl[1], Bl[2], Bl[3], blo + o);
                    #pragma unroll
                    for (int mi = 0; mi < MI; mi++) {
                        #pragma unroll
                        for (int h = 0; h < 2; h++) {
                            float* c = acc[mi][np * 2 + h];
                            mma_bf16(c, Ah[mi], Bh[h], Bh[2 + h]);
                            mma_bf16(c, Ah[mi], Bl[h], Bl[2 + h]);
                            mma_bf16(c, Al[mi], Bh[h], Bh[2 + h]);
                        }
                    }
                }
            }
        }

        if (more) {
            __syncthreads();               // everyone done reading buf^1 (iter i-1)
            char* st = smem + (buf ^ 1) * STAGE;
            #pragma unroll
            for (int j = 0; j < 8; j++) {
                int i4 = tid + 256 * j; int r = i4 >> 4, c4 = i4 & 15;
                uint32_t off = swz(r * 128 + c4 * 8);
                cvt_store(st + off, st + APB + off, ra[j]);
            }
            #pragma unroll
            for (int j = 0; j < BN / 16; j++) {
                int i4 = tid + 256 * j; int r = i4 >> 4, c4 = i4 & 15;
                uint32_t off = swz(r * 128 + c4 * 8);
                cvt_store(st + 2 * APB + off, st + 2 * APB + BPB + off, rb[j]);
            }
            __syncthreads();
        }
    }

    // ---- epilogue straight from accumulators
    const int* mrow = SCORES ? (mask + (long long)zb * maskld) : (const int*)0;
    #pragma unroll
    for (int mi = 0; mi < MI; mi++) {
        #pragma unroll
        for (int ni = 0; ni < NI; ni++) {
            int row0 = m0 + warp_m * WM + mi * 16 + (lane >> 2);
            int col0 = n0 + warp_n * WN + ni * 8 + (lane & 3) * 2;
            float v0 = acc[mi][ni][0], v1 = acc[mi][ni][1];
            float v2 = acc[mi][ni][2], v3 = acc[mi][ni][3];
            if (bias) {
                float b0 = bias[col0], b1 = bias[col0 + 1];
                v0 += b0; v1 += b1; v2 += b0; v3 += b1;
            }
            if (SCORES) {
                v0 *= scale; v1 *= scale; v2 *= scale; v3 *= scale;
                int mk0 = mrow[col0], mk1 = mrow[col0 + 1];
                int r1 = row0 + 8;
                if (col0 > row0     || mk0 == 0) v0 += MIN_VALF;
                if (col0 + 1 > row0 || mk1 == 0) v1 += MIN_VALF;
                if (col0 > r1       || mk0 == 0) v2 += MIN_VALF;
                if (col0 + 1 > r1   || mk1 == 0) v3 += MIN_VALF;
            }
            *(float2*)(Cb + (long long)row0 * ldc + col0) = make_float2(v0, v1);
            *(float2*)(Cb + (long long)(row0 + 8) * ldc + col0) = make_float2(v2, v3);
        }
    }
}

// ---------------- RMSNorm (in-place over rows) -------------------------------
__global__ void rmsnorm_kernel(float* __restrict__ x, const float* __restrict__ w, int D)
{
    long long row = blockIdx.x;
    float* p = x + row * D;
    __shared__ float red[256];
    int tid = threadIdx.x;
    float ss = 0.f;
    for (int i = tid; i < D; i += 256) { float v = p[i]; ss += v * v; }
    red[tid] = ss; __syncthreads();
    for (int s = 128; s > 0; s >>= 1) { if (tid < s) red[tid] += red[tid + s]; __syncthreads(); }
    float r = rsqrtf(red[0] / (float)D + 1e-6f);
    for (int i = tid; i < D; i += 256) p[i] = w[i] * p[i] * r;
}

// ---------------- KV prep: rmsnorm kv, rope k_pe -> g_kcat[row][576] ---------
__global__ void prep_kv_kernel(const float* __restrict__ kvfull,
                               const float* __restrict__ w,
                               float* __restrict__ kcat)
{
    int row = blockIdx.x;
    const float* in = kvfull + (long long)row * 576;
    float* out = kcat + (long long)row * 576;
    __shared__ float red[256];
    int tid = threadIdx.x;
    float ss = 0.f;
    for (int i = tid; i < 512; i += 256) { float v = in[i]; ss += v * v; }
    red[tid] = ss; __syncthreads();
    for (int s = 128; s > 0; s >>= 1) { if (tid < s) red[tid] += red[tid + s]; __syncthreads(); }
    float r = rsqrtf(red[0] / 512.0f + 1e-6f);
    for (int i = tid; i < 512; i += 256) out[i] = w[i] * in[i] * r;

    int pos = row & 2047;
    if (tid < 64) {
        int j = tid, jm = j & 31;
        float inv = (float)pow(10000.0, -(double)(2 * jm) / 64.0);
        float ang = (float)pos * inv;
        float c = cosf(ang), si = sinf(ang);
        float xj = in[512 + j];
        float other = (j < 32) ? -in[512 + j + 32] : in[512 + j - 32];
        out[512 + j] = xj * c + other * si;
    }
}

// ---------------- Q_pe rope: g_qb pe-slice -> g_qcat[...,512:576] ------------
__global__ void prep_qpe_kernel(const float* __restrict__ qb, float* __restrict__ qcat)
{
    int row = blockIdx.x;
    int pos = row & 2047;
    int b = row >> 11;
    int tid = threadIdx.x;
    for (int idx = tid; idx < 16 * 64; idx += blockDim.x) {
        int h = idx >> 6, j = idx & 63, jm = j & 31;
        float inv = (float)pow(10000.0, -(double)(2 * jm) / 64.0);
        float ang = (float)pos * inv;
        float c = cosf(ang), si = sinf(ang);
        const float* qp = qb + (long long)row * 3072 + h * 192 + 128;
        float xj = qp[j];
        float other = (j < 32) ? -qp[j + 32] : qp[j - 32];
        qcat[((long long)(b * 16 + h) * 2048 + pos) * 576 + 512 + j] = xj * c + other * si;
    }
}

// ---------------- row softmax over T=2048 (in place) -------------------------
__global__ void softmax_kernel(float* __restrict__ sc)
{
    long long row = blockIdx.x;
    float* p = sc + row * 2048;
    __shared__ float red[256];
    int tid = threadIdx.x;
    float m = -3.0e38f;
    for (int i = tid; i < 2048; i += 256) m = fmaxf(m, p[i]);
    red[tid] = m; __syncthreads();
    for (int s = 128; s > 0; s >>= 1) { if (tid < s) red[tid] = fmaxf(red[tid], red[tid + s]); __syncthreads(); }
    m = red[0]; __syncthreads();
    float sum = 0.f;
    for (int i = tid; i < 2048; i += 256) { float e = expf(p[i] - m); p[i] = e; sum += e; }
    red[tid] = sum; __syncthreads();
    for (int s = 128; s > 0; s >>= 1) { if (tid < s) red[tid] += red[tid + s]; __syncthreads(); }
    float inv = 1.0f / red[0];
    for (int i = tid; i < 2048; i += 256) p[i] *= inv;
}

// ---------------- transposes --------------------------------------------------
__global__ void transpose_kv_kernel(const float* __restrict__ kcat, float* __restrict__ kt)
{
    __shared__ float tile[32][33];
    int b = blockIdx.z;
    int t0 = blockIdx.x * 32, c0 = blockIdx.y * 32;
    int x = threadIdx.x, y = threadIdx.y;    // 32x8
    for (int yy = y; yy < 32; yy += 8)
        tile[yy][x] = kcat[((long long)(b * 2048 + t0 + yy)) * 576 + c0 + x];
    __syncthreads();
    for (int yy = y; yy < 32; yy += 8)
        kt[((long long)(b * 512 + c0 + yy)) * 2048 + t0 + x] = tile[x][yy];
}

__global__ void transpose_w_kernel(const float* __restrict__ w, float* __restrict__ wt)
{
    __shared__ float tile[32][33];
    int h = blockIdx.z;
    int d0 = blockIdx.x * 32, c0 = blockIdx.y * 32;
    int x = threadIdx.x, y = threadIdx.y;    // 32x8
    for (int yy = y; yy < 32; yy += 8)
        tile[yy][x] = w[(long long)h * 256 * 512 + (d0 + yy) * 512 + c0 + x];
    __syncthreads();
    for (int yy = y; yy < 32; yy += 8)
        wt[(long long)h * 512 * 128 + (c0 + yy) * 128 + d0 + x] = tile[x][yy];
}

// ---------------- launch -----------------------------------------------------
extern "C" void kernel_launch(void* const* d_in, const int* in_sizes, int n_in,
                              void* d_out, int out_size)
{
    const float* x        = (const float*)d_in[0];
    const int*   mask     = (const int*)  d_in[1];
    const float* wq_a_w   = (const float*)d_in[2];
    const float* wq_a_b   = (const float*)d_in[3];
    const float* q_norm_w = (const float*)d_in[4];
    const float* wq_b_w   = (const float*)d_in[5];
    const float* wq_b_b   = (const float*)d_in[6];
    const float* wkv_a_w  = (const float*)d_in[7];
    const float* wkv_a_b  = (const float*)d_in[8];
    const float* kv_norm_w= (const float*)d_in[9];
    const float* wkv_b_w  = (const float*)d_in[10];
    const float* wo_w     = (const float*)d_in[11];
    const float* wo_b     = (const float*)d_in[12];
    float* out = (float*)d_out;

    float *qa, *qb, *kvf, *kcat, *qcat, *sc, *ol, *ov, *kt, *wt1;
    cudaGetSymbolAddress((void**)&qa,   g_qa);
    cudaGetSymbolAddress((void**)&qb,   g_qb);
    cudaGetSymbolAddress((void**)&kvf,  g_kvfull);
    cudaGetSymbolAddress((void**)&kcat, g_kcat);
    cudaGetSymbolAddress((void**)&qcat, g_qcat);
    cudaGetSymbolAddress((void**)&sc,   g_scores);
    cudaGetSymbolAddress((void**)&ol,   g_olat);
    cudaGetSymbolAddress((void**)&ov,   g_ov);
    cudaGetSymbolAddress((void**)&kt,   g_kcatT);
    cudaGetSymbolAddress((void**)&wt1,  g_wT1);

    const int SM128 = 2 * (2 * 128 * 128 + 2 * 128 * 128); // 131072
    const int SM64  = 2 * (2 * 128 * 128 + 2 * 64 * 128);  // 98304
    cudaFuncSetAttribute((const void*)tgemm<128,false,false>, cudaFuncAttributeMaxDynamicSharedMemorySize, SM128);
    cudaFuncSetAttribute((const void*)tgemm<64,false,false>,  cudaFuncAttributeMaxDynamicSharedMemorySize, SM64);
    cudaFuncSetAttribute((const void*)tgemm<128,true,false>,  cudaFuncAttributeMaxDynamicSharedMemorySize, SM128);
    cudaFuncSetAttribute((const void*)tgemm<128,false,true>,  cudaFuncAttributeMaxDynamicSharedMemorySize, SM128);

    const float scale = rsqrtf(192.0f);

    // 1) q_a = x @ wq_a^T + b        [4096,1536] K=2048
    tgemm<128,false,false><<<dim3(12,32,1),256,SM128>>>(
        x, wq_a_w, wq_a_b, qa, 2048, 2048,2048,1536,
        0,0,0,0,0,0, 1, 0.f, 0, 0);
    // 2) rmsnorm(q_a)
    rmsnorm_kernel<<<4096,256>>>(qa, q_norm_w, 1536);
    // 3) q_b = q_a @ wq_b^T + b      [4096,3072] K=1536
    tgemm<128,false,false><<<dim3(24,32,1),256,SM128>>>(
        qa, wq_b_w, wq_b_b, qb, 1536, 1536,1536,3072,
        0,0,0,0,0,0, 1, 0.f, 0, 0);
    // 4) kv_full = x @ wkv_a^T + b   [4096,576] K=2048
    tgemm<64,false,false><<<dim3(9,32,1),256,SM64>>>(
        x, wkv_a_w, wkv_a_b, kvf, 2048, 2048,2048,576,
        0,0,0,0,0,0, 1, 0.f, 0, 0);
    // 5) kv rmsnorm + k_pe rope -> kcat
    prep_kv_kernel<<<4096,256>>>(kvf, kv_norm_w, kcat);
    // 6) q_pe rope -> qcat[...,512:576]
    prep_qpe_kernel<<<4096,256>>>(qb, qcat);
    // 7) transposes: kcat latent -> kcatT [b][512][2048]; wkv_b nope -> wT1 [h][512][128]
    transpose_kv_kernel<<<dim3(64,16,2),dim3(32,8)>>>(kcat, kt);
    transpose_w_kernel<<<dim3(4,16,16),dim3(32,8)>>>(wkv_b_w, wt1);
    // 8) q_lat[b,h] = q_nope @ wT1[h]^T -> qcat[...,0:512]   K=128
    tgemm<128,false,false><<<dim3(4,16,32),256,SM128>>>(
        qb, wt1, 0, qcat, 128, 3072,128,576,
        2048LL*3072, 192, 0, 512LL*128, 16LL*2048*576, 2048LL*576, 16,
        0.f, 0, 0);
    // 9) scores[b,h] = qcat @ kcat^T * scale + mask   K=576
    tgemm<128,true,false><<<dim3(16,16,32),256,SM128>>>(
        qcat, kcat, 0, sc, 576, 576,576,2048,
        16LL*2048*576, 2048LL*576, 2048LL*576, 0,
        16LL*2048*2048, 2048LL*2048, 16, scale, mask, 2048);
    // 10) softmax rows
    softmax_kernel<<<2*16*2048,256>>>(sc);
    // 11) olat[b,h] = attn @ kcatT^T  (causal K-trunc)  K=2048
    tgemm<128,false,true><<<dim3(4,16,32),256,SM128>>>(
        sc, kt, 0, ol, 2048, 2048,2048,512,
        16LL*2048*2048, 2048LL*2048, 512LL*2048, 0,
        16LL*2048*512, 2048LL*512, 16, 0.f, 0, 0);
    // 12) ov[b,s,h*128+d] = olat @ wkv_b[h,128:,:]^T   K=512
    tgemm<128,false,false><<<dim3(1,16,32),256,SM128>>>(
        ol, wkv_b_w + 128LL*512, 0, ov, 512, 512,512,2048,
        16LL*2048*512, 2048LL*512, 0, 256LL*512,
        2048LL*2048, 128, 16, 0.f, 0, 0);
    // 13) out = ov @ wo^T + b        [4096,2048] K=2048
    tgemm<128,false,false><<<dim3(16,32,1),256,SM128>>>(
        ov, wo_w, wo_b, out, 2048, 2048,2048,2048,
        0,0,0,0,0,0, 1, 0.f, 0, 0);
}

// round 5
// speedup vs baseline: 3.1735x; 1.1617x over previous
#include <cuda_runtime.h>
#include <cuda_bf16.h>
#include <math.h>
#include <stdint.h>

// ---------------- lo-plane offsets (elements) ---------------------------------
#define LO_X    8388608LL
#define LO_WQA  3145728LL
#define LO_WQB  4718592LL
#define LO_WKVA 1179648LL
#define LO_WO   4194304LL
#define LO_WV   1048576LL
#define LO_WT1  1048576LL
#define LO_QA   6291456LL
#define LO_QB   12582912LL
#define LO_KC   2359296LL
#define LO_KT   2097152LL
#define LO_QC   37748736LL
#define LO_SC   134217728LL
#define LO_OL   33554432LL
#define LO_OV   8388608LL

// ---------------- scratch (device globals) -----------------------------------
__device__ __nv_bfloat16 g_xhl[2 * LO_X];
__device__ __nv_bfloat16 g_wqahl[2 * LO_WQA];
__device__ __nv_bfloat16 g_wqbhl[2 * LO_WQB];
__device__ __nv_bfloat16 g_wkvahl[2 * LO_WKVA];
__device__ __nv_bfloat16 g_wohl[2 * LO_WO];
__device__ __nv_bfloat16 g_wvhl[2 * LO_WV];
__device__ __nv_bfloat16 g_wt1hl[2 * LO_WT1];
__device__ float g_qa[4096LL * 1536];
__device__ __nv_bfloat16 g_qahl[2 * LO_QA];
__device__ __nv_bfloat16 g_qbhl[2 * LO_QB];
__device__ float g_kvfull[4096LL * 576];
__device__ __nv_bfloat16 g_kcathl[2 * LO_KC];
__device__ __nv_bfloat16 g_kcatThl[2 * LO_KT];
__device__ __nv_bfloat16 g_qcathl[2 * LO_QC];
__device__ float g_scores[2LL * 16 * 2048 * 2048];
__device__ __nv_bfloat16 g_schl[2 * LO_SC];
__device__ __nv_bfloat16 g_olathl[2 * LO_OL];
__device__ __nv_bfloat16 g_ovhl[2 * LO_OV];

// ---------------- helpers ----------------------------------------------------
__device__ __forceinline__ uint32_t smem_u32(const void* p) {
    uint32_t a;
    asm("{ .reg .u64 t; cvta.to.shared.u64 t, %1; cvt.u32.u64 %0, t; }" : "=r"(a) : "l"(p));
    return a;
}
__device__ __forceinline__ uint32_t swz(uint32_t o) { return o ^ ((o >> 3) & 0x70); }

__device__ __forceinline__ void ldm_x4(uint32_t& r0, uint32_t& r1, uint32_t& r2, uint32_t& r3,
                                       uint32_t addr) {
    asm volatile("ldmatrix.sync.aligned.m8n8.x4.shared.b16 {%0,%1,%2,%3}, [%4];"
                 : "=r"(r0), "=r"(r1), "=r"(r2), "=r"(r3) : "r"(addr));
}
__device__ __forceinline__ void mma_bf16(float* d, const uint32_t* a, uint32_t b0, uint32_t b1) {
    asm volatile("mma.sync.aligned.m16n8k16.row.col.f32.bf16.bf16.f32 "
                 "{%0,%1,%2,%3},{%4,%5,%6,%7},{%8,%9},{%0,%1,%2,%3};"
                 : "+f"(d[0]), "+f"(d[1]), "+f"(d[2]), "+f"(d[3])
                 : "r"(a[0]), "r"(a[1]), "r"(a[2]), "r"(a[3]), "r"(b0), "r"(b1));
}
__device__ __forceinline__ void cp16(uint32_t dst, const void* src) {
    asm volatile("cp.async.cg.shared.global [%0], [%1], 16;" :: "r"(dst), "l"(src));
}
#define CP_COMMIT() asm volatile("cp.async.commit_group;" ::: "memory")

__device__ __forceinline__ void split2(float a, float b, __nv_bfloat162& h, __nv_bfloat162& l) {
    h = __floats2bfloat162_rn(a, b);
    l = __floats2bfloat162_rn(a - __low2float(h), b - __high2float(h));
}
__device__ __forceinline__ void split_store(__nv_bfloat16* p, long long loOff, long long idx, float v) {
    __nv_bfloat16 h = __float2bfloat16(v);
    p[idx] = h;
    p[idx + loOff] = __float2bfloat16(v - __bfloat162float(h));
}
__device__ __forceinline__ float join(const __nv_bfloat16* p, long long loOff, long long idx) {
    return __bfloat162float(p[idx]) + __bfloat162float(p[idx + loOff]);
}

// ---------------- tensor-core GEMM: C[m,n] = sum_k A[m,k]*B[n,k] --------------
// A,B: bf16 hi/lo planes (lo at +aLo/+bLo). cp.async double-buffered, BK=64.
// 3-pass split mma: hi*hi + hi*lo + lo*hi, fp32 accum.
// SCORES: skip tiles fully above diagonal (no write), epilogue scales only.
// CAUSALA: truncate K at m0+128.  OUTHL: write C as bf16 hi/lo planes.
template<int BN, bool SCORES, bool CAUSALA, bool OUTHL>
__global__ __launch_bounds__(256, 1)
void tgemm(const __nv_bfloat16* __restrict__ A, const __nv_bfloat16* __restrict__ B,
           const float* __restrict__ bias, void* __restrict__ C,
           int K, int lda, int ldb, int ldc,
           long long aLo, long long bLo, long long cLo,
           long long sAb, long long sAh, long long sBb, long long sBh,
           long long sCb, long long sCh, int nh, float scale)
{
    constexpr int APB = 128 * 128;           // A plane bytes per stage (128 rows x 128B)
    constexpr int BPB = BN * 128;
    constexpr int STAGE = 2 * APB + 2 * BPB;
    constexpr int NWM = (BN == 128) ? 4 : 8;
    constexpr int WM  = 128 / NWM;
    constexpr int WN  = 64;
    constexpr int MI  = WM / 16;
    constexpr int NI  = WN / 8;

    extern __shared__ __align__(1024) char smem[];

    int tid = threadIdx.x;
    int wid = tid >> 5, lane = tid & 31;
    int warp_m = wid % NWM, warp_n = wid / NWM;

    int z = blockIdx.z, zb = z / nh, zh = z - zb * nh;
    int m0 = blockIdx.y * 128, n0 = blockIdx.x * BN;

    if (SCORES && n0 >= m0 + 128) return;    // never read by softmax

    const __nv_bfloat16* Ap = A + zb * sAb + zh * sAh + (long long)m0 * lda;
    const __nv_bfloat16* Bp = B + zb * sBb + zh * sBh + (long long)n0 * ldb;

    int kend = CAUSALA ? min(K, m0 + 128) : K;
    int nt = kend >> 6;

    uint32_t sbase = smem_u32(smem);

    float acc[MI][NI][4];
    #pragma unroll
    for (int mi = 0; mi < MI; mi++)
        #pragma unroll
        for (int ni = 0; ni < NI; ni++)
            #pragma unroll
            for (int q = 0; q < 4; q++) acc[mi][ni][q] = 0.f;

    auto issue = [&](int kt, int buf) {
        uint32_t sb = sbase + buf * STAGE;
        const __nv_bfloat16* As = Ap + (kt << 6);
        const __nv_bfloat16* Bs = Bp + (kt << 6);
        #pragma unroll
        for (int j = 0; j < 4; j++) {
            int c = tid + 256 * j; int r = c >> 3, ch = c & 7;
            uint32_t d = swz(r * 128 + ch * 16);
            const __nv_bfloat16* s = As + (long long)r * lda + ch * 8;
            cp16(sb + d, s);
            cp16(sb + APB + d, s + aLo);
        }
        #pragma unroll
        for (int j = 0; j < BN / 32; j++) {
            int c = tid + 256 * j; int r = c >> 3, ch = c & 7;
            uint32_t d = swz(r * 128 + ch * 16);
            const __nv_bfloat16* s = Bs + (long long)r * ldb + ch * 8;
            cp16(sb + 2 * APB + d, s);
            cp16(sb + 2 * APB + BPB + d, s + bLo);
        }
    };

    issue(0, 0); CP_COMMIT();
    if (nt > 1) { issue(1, 1); CP_COMMIT(); }

    for (int i = 0; i < nt; i++) {
        int buf = i & 1;
        if (i + 1 < nt) { asm volatile("cp.async.wait_group 1;" ::: "memory"); }
        else            { asm volatile("cp.async.wait_group 0;" ::: "memory"); }
        __syncthreads();

        uint32_t ahi = sbase + buf * STAGE;
        uint32_t alo = ahi + APB;
        uint32_t bhi = ahi + 2 * APB;
        uint32_t blo = bhi + BPB;
        int rsel = (lane & 7) + ((lane >> 3) & 1) * 8;
        #pragma unroll
        for (int kk = 0; kk < 4; kk++) {
            uint32_t cb = kk * 32 + ((lane >> 4) & 1) * 16;
            uint32_t Ah[MI][4], Al[MI][4];
            #pragma unroll
            for (int mi = 0; mi < MI; mi++) {
                uint32_t o = swz((warp_m * WM + mi * 16 + rsel) * 128 + cb);
                ldm_x4(Ah[mi][0], Ah[mi][1], Ah[mi][2], Ah[mi][3], ahi + o);
                ldm_x4(Al[mi][0], Al[mi][1], Al[mi][2], Al[mi][3], alo + o);
            }
            #pragma unroll
            for (int np = 0; np < NI / 2; np++) {
                uint32_t o = swz((warp_n * WN + np * 16 + rsel) * 128 + cb);
                uint32_t Bh[4], Bl[4];
                ldm_x4(Bh[0], Bh[1], Bh[2], Bh[3], bhi + o);
                ldm_x4(Bl[0], Bl[1], Bl[2], Bl[3], blo + o);
                #pragma unroll
                for (int mi = 0; mi < MI; mi++) {
                    #pragma unroll
                    for (int h = 0; h < 2; h++) {
                        float* c = acc[mi][np * 2 + h];
                        mma_bf16(c, Ah[mi], Bh[h], Bh[2 + h]);
                        mma_bf16(c, Ah[mi], Bl[h], Bl[2 + h]);
                        mma_bf16(c, Al[mi], Bh[h], Bh[2 + h]);
                    }
                }
            }
        }

        if (i + 2 < nt) {
            __syncthreads();
            issue(i + 2, buf);
            CP_COMMIT();
        }
    }

    // ---- epilogue
    #pragma unroll
    for (int mi = 0; mi < MI; mi++) {
        #pragma unroll
        for (int ni = 0; ni < NI; ni++) {
            int row0 = m0 + warp_m * WM + mi * 16 + (lane >> 2);
            int col0 = n0 + warp_n * WN + ni * 8 + (lane & 3) * 2;
            float v0 = acc[mi][ni][0], v1 = acc[mi][ni][1];
            float v2 = acc[mi][ni][2], v3 = acc[mi][ni][3];
            if (bias) {
                float b0 = bias[col0], b1 = bias[col0 + 1];
                v0 += b0; v1 += b1; v2 += b0; v3 += b1;
            }
            if (SCORES) { v0 *= scale; v1 *= scale; v2 *= scale; v3 *= scale; }
            long long i0 = (long long)row0 * ldc + col0;
            long long i1 = (long long)(row0 + 8) * ldc + col0;
            if (OUTHL) {
                __nv_bfloat16* Ch = (__nv_bfloat16*)C + zb * sCb + zh * sCh;
                __nv_bfloat162 h, l;
                split2(v0, v1, h, l);
                *(__nv_bfloat162*)(Ch + i0) = h;
                *(__nv_bfloat162*)(Ch + cLo + i0) = l;
                split2(v2, v3, h, l);
                *(__nv_bfloat162*)(Ch + i1) = h;
                *(__nv_bfloat162*)(Ch + cLo + i1) = l;
            } else {
                float* Cf = (float*)C + zb * sCb + zh * sCh;
                *(float2*)(Cf + i0) = make_float2(v0, v1);
                *(float2*)(Cf + i1) = make_float2(v2, v3);
            }
        }
    }
}

// ---------------- fp32 -> hi/lo bf16 planes (vectorized) ----------------------
__global__ void cvt_hl4(const float4* __restrict__ src, __nv_bfloat16* __restrict__ dst,
                        long long n4, long long loOff)
{
    long long i = (long long)blockIdx.x * 256 + threadIdx.x;
    if (i >= n4) return;
    float4 v = src[i];
    __nv_bfloat162 h01, l01, h23, l23;
    split2(v.x, v.y, h01, l01);
    split2(v.z, v.w, h23, l23);
    *(__nv_bfloat162*)(dst + i * 4) = h01;
    *(__nv_bfloat162*)(dst + i * 4 + 2) = h23;
    *(__nv_bfloat162*)(dst + loOff + i * 4) = l01;
    *(__nv_bfloat162*)(dst + loOff + i * 4 + 2) = l23;
}

// wkv_b value-part (head-strided rows) -> compact hi/lo [h*128+d][512]
__global__ void cvt_wv(const float* __restrict__ src, __nv_bfloat16* __restrict__ dst, long long loOff)
{
    int r = blockIdx.x;                                   // 0..2047
    const float* s = src + ((long long)(r >> 7) * 256 + 128 + (r & 127)) * 512;
    long long base = (long long)r * 512;
    for (int i = threadIdx.x; i < 512; i += 256)
        split_store(dst, loOff, base + i, s[i]);
}

// ---------------- RMSNorm -> hi/lo -------------------------------------------
__global__ void rmsnorm_hl(const float* __restrict__ x, const float* __restrict__ w,
                           __nv_bfloat16* __restrict__ out, int D, long long loOff)
{
    long long row = blockIdx.x;
    const float* p = x + row * D;
    __shared__ float red[256];
    int tid = threadIdx.x;
    float ss = 0.f;
    for (int i = tid; i < D; i += 256) { float v = p[i]; ss += v * v; }
    red[tid] = ss; __syncthreads();
    for (int s = 128; s > 0; s >>= 1) { if (tid < s) red[tid] += red[tid + s]; __syncthreads(); }
    float r = rsqrtf(red[0] / (float)D + 1e-6f);
    for (int i = tid; i < D; i += 256)
        split_store(out, loOff, row * D + i, w[i] * p[i] * r);
}

// ---------------- KV prep: rmsnorm + rope -> kcathl ---------------------------
__global__ void prep_kv_hl(const float* __restrict__ kvfull, const float* __restrict__ w,
                           __nv_bfloat16* __restrict__ kc, long long loOff)
{
    int row = blockIdx.x;
    const float* in = kvfull + (long long)row * 576;
    long long base = (long long)row * 576;
    __shared__ float red[256];
    int tid = threadIdx.x;
    float ss = 0.f;
    for (int i = tid; i < 512; i += 256) { float v = in[i]; ss += v * v; }
    red[tid] = ss; __syncthreads();
    for (int s = 128; s > 0; s >>= 1) { if (tid < s) red[tid] += red[tid + s]; __syncthreads(); }
    float r = rsqrtf(red[0] / 512.0f + 1e-6f);
    for (int i = tid; i < 512; i += 256)
        split_store(kc, loOff, base + i, w[i] * in[i] * r);

    int pos = row & 2047;
    if (tid < 64) {
        int j = tid, jm = j & 31;
        float inv = (float)pow(10000.0, -(double)(2 * jm) / 64.0);
        float ang = (float)pos * inv;
        float c = cosf(ang), si = sinf(ang);
        float xj = in[512 + j];
        float other = (j < 32) ? -in[512 + j + 32] : in[512 + j - 32];
        split_store(kc, loOff, base + 512 + j, xj * c + other * si);
    }
}

// ---------------- Q_pe rope: qbhl -> qcathl[...,512:576] ----------------------
__global__ void prep_qpe_hl(const __nv_bfloat16* __restrict__ qb, __nv_bfloat16* __restrict__ qc,
                            long long qbLo, long long qcLo)
{
    int row = blockIdx.x;
    int pos = row & 2047;
    int b = row >> 11;
    int tid = threadIdx.x;
    for (int idx = tid; idx < 16 * 64; idx += blockDim.x) {
        int h = idx >> 6, j = idx & 63, jm = j & 31;
        float inv = (float)pow(10000.0, -(double)(2 * jm) / 64.0);
        float ang = (float)pos * inv;
        float c = cosf(ang), si = sinf(ang);
        long long base = (long long)row * 3072 + h * 192 + 128;
        float xj = join(qb, qbLo, base + j);
        float other = (j < 32) ? -join(qb, qbLo, base + j + 32) : join(qb, qbLo, base + j - 32);
        long long o = ((long long)(b * 16 + h) * 2048 + pos) * 576 + 512 + j;
        split_store(qc, qcLo, o, xj * c + other * si);
    }
}

// ---------------- softmax: fp32 scores -> probs hi/lo, causal+mask ------------
__global__ void softmax_hl(const float* __restrict__ sc, __nv_bfloat16* __restrict__ pr,
                           const int* __restrict__ mask, long long loOff)
{
    long long row = blockIdx.x;
    int m = (int)(row & 2047);
    int b = (int)(row >> 15);
    const float* p = sc + row * 2048;
    __nv_bfloat16* o = pr + row * 2048;
    const int* mk = mask + (long long)b * 2048;
    __shared__ float buf[2048];
    __shared__ float red[256];
    int tid = threadIdx.x;
    int lim = ((m + 128) >> 7) << 7;          // PV reads only up to this boundary
    float mx = -3.0e38f;
    for (int t = tid; t <= m; t += 256) if (mk[t]) mx = fmaxf(mx, p[t]);
    red[tid] = mx; __syncthreads();
    for (int s = 128; s > 0; s >>= 1) { if (tid < s) red[tid] = fmaxf(red[tid], red[tid + s]); __syncthreads(); }
    mx = red[0]; __syncthreads();
    if (mx <= -2.9e38f) {                      // fully masked row -> uniform (matches ref)
        __nv_bfloat16 u = __float2bfloat16(1.0f / 2048.0f);
        __nv_bfloat16 zz = __float2bfloat16(0.0f);
        for (int t = tid; t < 2048; t += 256) { o[t] = u; o[t + loOff] = zz; }
        return;
    }
    float s = 0.f;
    for (int t = tid; t < lim; t += 256) {
        float e = (t <= m && mk[t]) ? expf(p[t] - mx) : 0.f;
        buf[t] = e; s += e;
    }
    red[tid] = s; __syncthreads();
    for (int st = 128; st > 0; st >>= 1) { if (tid < st) red[tid] += red[tid + st]; __syncthreads(); }
    float inv = 1.0f / red[0];
    for (int t = tid; t < lim; t += 256)
        split_store(o, loOff, t, buf[t] * inv);
}

// ---------------- transposes (bf16 planes / fp32->hl) --------------------------
__global__ void transpose_kv_hl(const __nv_bfloat16* __restrict__ kc, __nv_bfloat16* __restrict__ kt,
                                long long inLo, long long outLo)
{
    __shared__ __nv_bfloat16 tile[32][33];
    int b = blockIdx.z;
    int t0 = blockIdx.x * 32, c0 = blockIdx.y * 32;
    int x = threadIdx.x, y = threadIdx.y;      // 32x8
    #pragma unroll
    for (int p = 0; p < 2; p++) {
        const __nv_bfloat16* src = kc + p * inLo;
        __nv_bfloat16* dst = kt + p * outLo;
        for (int yy = y; yy < 32; yy += 8)
            tile[yy][x] = src[((long long)(b * 2048 + t0 + yy)) * 576 + c0 + x];
        __syncthreads();
        for (int yy = y; yy < 32; yy += 8)
            dst[((long long)(b * 512 + c0 + yy)) * 2048 + t0 + x] = tile[x][yy];
        __syncthreads();
    }
}

__global__ void transpose_w_hl(const float* __restrict__ w, __nv_bfloat16* __restrict__ wt, long long loOff)
{
    __shared__ float tile[32][33];
    int h = blockIdx.z;
    int d0 = blockIdx.x * 32, c0 = blockIdx.y * 32;
    int x = threadIdx.x, y = threadIdx.y;      // 32x8
    for (int yy = y; yy < 32; yy += 8)
        tile[yy][x] = w[(long long)h * 256 * 512 + (d0 + yy) * 512 + c0 + x];
    __syncthreads();
    for (int yy = y; yy < 32; yy += 8)
        split_store(wt, loOff, (long long)h * 512 * 128 + (c0 + yy) * 128 + d0 + x, tile[x][yy]);
}

// ---------------- launch -----------------------------------------------------
extern "C" void kernel_launch(void* const* d_in, const int* in_sizes, int n_in,
                              void* d_out, int out_size)
{
    const float* x        = (const float*)d_in[0];
    const int*   mask     = (const int*)  d_in[1];
    const float* wq_a_w   = (const float*)d_in[2];
    const float* wq_a_b   = (const float*)d_in[3];
    const float* q_norm_w = (const float*)d_in[4];
    const float* wq_b_w   = (const float*)d_in[5];
    const float* wq_b_b   = (const float*)d_in[6];
    const float* wkv_a_w  = (const float*)d_in[7];
    const float* wkv_a_b  = (const float*)d_in[8];
    const float* kv_norm_w= (const float*)d_in[9];
    const float* wkv_b_w  = (const float*)d_in[10];
    const float* wo_w     = (const float*)d_in[11];
    const float* wo_b     = (const float*)d_in[12];
    float* out = (float*)d_out;

    __nv_bfloat16 *xhl, *wqahl, *wqbhl, *wkvahl, *wohl, *wvhl, *wt1hl;
    __nv_bfloat16 *qahl, *qbhl, *kchl, *kthl, *qchl, *schl, *olhl, *ovhl;
    float *qa, *kvf, *sc;
    cudaGetSymbolAddress((void**)&xhl,   g_xhl);
    cudaGetSymbolAddress((void**)&wqahl, g_wqahl);
    cudaGetSymbolAddress((void**)&wqbhl, g_wqbhl);
    cudaGetSymbolAddress((void**)&wkvahl,g_wkvahl);
    cudaGetSymbolAddress((void**)&wohl,  g_wohl);
    cudaGetSymbolAddress((void**)&wvhl,  g_wvhl);
    cudaGetSymbolAddress((void**)&wt1hl, g_wt1hl);
    cudaGetSymbolAddress((void**)&qa,    g_qa);
    cudaGetSymbolAddress((void**)&qahl,  g_qahl);
    cudaGetSymbolAddress((void**)&qbhl,  g_qbhl);
    cudaGetSymbolAddress((void**)&kvf,   g_kvfull);
    cudaGetSymbolAddress((void**)&kchl,  g_kcathl);
    cudaGetSymbolAddress((void**)&kthl,  g_kcatThl);
    cudaGetSymbolAddress((void**)&qchl,  g_qcathl);
    cudaGetSymbolAddress((void**)&sc,    g_scores);
    cudaGetSymbolAddress((void**)&schl,  g_schl);
    cudaGetSymbolAddress((void**)&olhl,  g_olathl);
    cudaGetSymbolAddress((void**)&ovhl,  g_ovhl);

    const int SM128 = 2 * (2 * 16384 + 2 * 128 * 128);   // 131072
    const int SM64  = 2 * (2 * 16384 + 2 * 64 * 128);    // 98304
    cudaFuncSetAttribute((const void*)tgemm<128,false,false,false>, cudaFuncAttributeMaxDynamicSharedMemorySize, SM128);
    cudaFuncSetAttribute((const void*)tgemm<128,false,false,true>,  cudaFuncAttributeMaxDynamicSharedMemorySize, SM128);
    cudaFuncSetAttribute((const void*)tgemm<64,false,false,false>,  cudaFuncAttributeMaxDynamicSharedMemorySize, SM64);
    cudaFuncSetAttribute((const void*)tgemm<128,true,false,false>,  cudaFuncAttributeMaxDynamicSharedMemorySize, SM128);
    cudaFuncSetAttribute((const void*)tgemm<128,false,true,true>,   cudaFuncAttributeMaxDynamicSharedMemorySize, SM128);

    const float scale = rsqrtf(192.0f);

    // ---- operand conversions (independent)
    cvt_hl4<<<8192,256>>>((const float4*)x,       xhl,    2097152, LO_X);
    cvt_hl4<<<3072,256>>>((const float4*)wq_a_w,  wqahl,   786432, LO_WQA);
    cvt_hl4<<<4608,256>>>((const float4*)wq_b_w,  wqbhl,  1179648, LO_WQB);
    cvt_hl4<<<1152,256>>>((const float4*)wkv_a_w, wkvahl,  294912, LO_WKVA);
    cvt_hl4<<<4096,256>>>((const float4*)wo_w,    wohl,   1048576, LO_WO);
    cvt_wv<<<2048,256>>>(wkv_b_w, wvhl, LO_WV);
    transpose_w_hl<<<dim3(4,16,16),dim3(32,8)>>>(wkv_b_w, wt1hl, LO_WT1);

    // 1) q_a = x @ wq_a^T + b   [4096,1536] K=2048  -> fp32
    tgemm<128,false,false,false><<<dim3(12,32,1),256,SM128>>>(
        xhl, wqahl, wq_a_b, qa, 2048, 2048,2048,1536,
        LO_X, LO_WQA, 0, 0,0,0,0, 0,0, 1, 0.f);
    // 2) rmsnorm -> qahl
    rmsnorm_hl<<<4096,256>>>(qa, q_norm_w, qahl, 1536, LO_QA);
    // 3) q_b = qa @ wq_b^T + b  [4096,3072] K=1536  -> qbhl
    tgemm<128,false,false,true><<<dim3(24,32,1),256,SM128>>>(
        qahl, wqbhl, wq_b_b, qbhl, 1536, 1536,1536,3072,
        LO_QA, LO_WQB, LO_QB, 0,0,0,0, 0,0, 1, 0.f);
    // 4) kv_full = x @ wkv_a^T + b  [4096,576] K=2048 -> fp32
    tgemm<64,false,false,false><<<dim3(9,32,1),256,SM64>>>(
        xhl, wkvahl, wkv_a_b, kvf, 2048, 2048,2048,576,
        LO_X, LO_WKVA, 0, 0,0,0,0, 0,0, 1, 0.f);
    // 5) kv rmsnorm + k_pe rope -> kcathl
    prep_kv_hl<<<4096,256>>>(kvf, kv_norm_w, kchl, LO_KC);
    // 6) kcat latent transpose -> kcatThl
    transpose_kv_hl<<<dim3(64,16,2),dim3(32,8)>>>(kchl, kthl, LO_KC, LO_KT);
    // 7) q_pe rope -> qcathl[...,512:576]
    prep_qpe_hl<<<4096,256>>>(qbhl, qchl, LO_QB, LO_QC);
    // 8) q_lat = q_nope @ wT1^T  K=128 -> qcathl[...,0:512]
    tgemm<128,false,false,true><<<dim3(4,16,32),256,SM128>>>(
        qbhl, wt1hl, 0, qchl, 128, 3072,128,576,
        LO_QB, LO_WT1, LO_QC, 2048LL*3072, 192, 0, 512LL*128,
        16LL*2048*576, 2048LL*576, 16, 0.f);
    // 9) scores = qcat @ kcat^T * scale   K=576 -> fp32 (lower-tri tiles only)
    tgemm<128,true,false,false><<<dim3(16,16,32),256,SM128>>>(
        qchl, kchl, 0, sc, 576, 576,576,2048,
        LO_QC, LO_KC, 0, 16LL*2048*576, 2048LL*576, 2048LL*576, 0,
        16LL*2048*2048, 2048LL*2048, 16, scale);
    // 10) softmax (causal+mask) -> schl
    softmax_hl<<<2*16*2048,256>>>(sc, schl, mask, LO_SC);
    // 11) olat = probs @ kcatT^T  (K-trunc)  K=2048 -> olathl
    tgemm<128,false,true,true><<<dim3(4,16,32),256,SM128>>>(
        schl, kthl, 0, olhl, 2048, 2048,2048,512,
        LO_SC, LO_KT, LO_OL, 16LL*2048*2048, 2048LL*2048, 512LL*2048, 0,
        16LL*2048*512, 2048LL*512, 16, 0.f);
    // 12) ov = olat @ wv^T  K=512 -> ovhl
    tgemm<128,false,false,true><<<dim3(1,16,32),256,SM128>>>(
        olhl, wvhl, 0, ovhl, 512, 512,512,2048,
        LO_OL, LO_WV, LO_OV, 16LL*2048*512, 2048LL*512, 0, 128LL*512,
        2048LL*2048, 128, 16, 0.f);
    // 13) out = ov @ wo^T + b  [4096,2048] K=2048 -> fp32
    tgemm<128,false,false,false><<<dim3(16,32,1),256,SM128>>>(
        ovhl, wohl, wo_b, out, 2048, 2048,2048,2048,
        LO_OV, LO_WO, 0, 0,0,0,0, 0,0, 1, 0.f);
}